// round 12
// baseline (speedup 1.0000x reference)
#include <cuda_runtime.h>
#include <cuda_bf16.h>
#include <math.h>
#include <stdint.h>

// Problem constants (fixed shapes)
#define T_STEPS 2048
#define BATCH   256
#define HID     256
#define OUT_DIM 16

// Scratch (device globals: allocation-free kernel_launch)
__device__ float g_xp[134217728];          // [T][B][H] fp32, 512 MB
__device__ float g_hfinal[BATCH * HID];
__device__ __nv_bfloat16 g_xhi[134217728]; // x hi split, 256 MB
__device__ __nv_bfloat16 g_xlo[134217728]; // x lo split, 256 MB
__device__ __nv_bfloat16 g_WThi[65536];    // W_ih^T hi: [n][k]
__device__ __nv_bfloat16 g_WTlo[65536];    // W_ih^T lo: [n][k]

// ---------------------------------------------------------------------------
// helpers
// ---------------------------------------------------------------------------
__device__ __forceinline__ uint32_t smem_u32(const void* p) {
    uint32_t a;
    asm("{ .reg .u64 t; cvta.to.shared.u64 t, %1; cvt.u32.u64 %0, t; }"
        : "=r"(a) : "l"(p));
    return a;
}
__device__ __forceinline__ void cp16(uint32_t dst, const void* src) {
    asm volatile("cp.async.cg.shared.global [%0], [%1], 16;"
                 :: "r"(dst), "l"(src) : "memory");
}
__device__ __forceinline__ void ldsm_x4(uint32_t* r, uint32_t addr) {
    asm volatile("ldmatrix.sync.aligned.m8n8.x4.shared.b16 {%0,%1,%2,%3}, [%4];"
                 : "=r"(r[0]), "=r"(r[1]), "=r"(r[2]), "=r"(r[3]) : "r"(addr));
}
__device__ __forceinline__ void ldsm_x2(uint32_t* r, uint32_t addr) {
    asm volatile("ldmatrix.sync.aligned.m8n8.x2.shared.b16 {%0,%1}, [%2];"
                 : "=r"(r[0]), "=r"(r[1]) : "r"(addr));
}
__device__ __forceinline__ void mma_bf16(float* c, const uint32_t* a, const uint32_t* b) {
    asm volatile(
        "mma.sync.aligned.m16n8k16.row.col.f32.bf16.bf16.f32 "
        "{%0,%1,%2,%3}, {%4,%5,%6,%7}, {%8,%9}, {%0,%1,%2,%3};"
        : "+f"(c[0]), "+f"(c[1]), "+f"(c[2]), "+f"(c[3])
        : "r"(a[0]), "r"(a[1]), "r"(a[2]), "r"(a[3]), "r"(b[0]), "r"(b[1]));
}

// f32x2 helpers
__device__ __forceinline__ unsigned long long f32x2_pack(float x, float y) {
    unsigned long long r;
    asm("mov.b64 %0, {%1, %2};" : "=l"(r) : "r"(__float_as_uint(x)), "r"(__float_as_uint(y)));
    return r;
}
__device__ __forceinline__ void f32x2_unpack(unsigned long long v, float& x, float& y) {
    unsigned int lo, hi;
    asm("mov.b64 {%0, %1}, %2;" : "=r"(lo), "=r"(hi) : "l"(v));
    x = __uint_as_float(lo);
    y = __uint_as_float(hi);
}
__device__ __forceinline__ void ffma2(unsigned long long& acc,
                                      unsigned long long a, unsigned long long b) {
    asm("fma.rn.f32x2 %0, %1, %2, %0;" : "+l"(acc) : "l"(a), "l"(b));
}
__device__ __forceinline__ void fadd2(unsigned long long& acc, unsigned long long b) {
    asm("add.rn.f32x2 %0, %0, %1;" : "+l"(acc) : "l"(b));
}

// ---------------------------------------------------------------------------
// Kernel 0a: W_ih [k][n] -> transposed bf16 hi/lo [n][k]
// ---------------------------------------------------------------------------
__global__ __launch_bounds__(256)
void prep_w_kernel(const float* __restrict__ Wih) {
    int n = blockIdx.x;
    int k = threadIdx.x;
    float w = Wih[k * 256 + n];
    __nv_bfloat16 hi = __float2bfloat16(w);
    float lof = w - __bfloat162float(hi);
    g_WThi[n * 256 + k] = hi;
    g_WTlo[n * 256 + k] = __float2bfloat16(lof);
}

// ---------------------------------------------------------------------------
// Kernel 0b: x fp32 -> bf16 hi/lo splits (streaming)
// ---------------------------------------------------------------------------
__global__ __launch_bounds__(256)
void prep_x_kernel(const float* __restrict__ x) {
    size_t i = ((size_t)blockIdx.x * 256 + threadIdx.x) * 4;
    float4 f = *(const float4*)&x[i];
    __nv_bfloat162 h0 = __float22bfloat162_rn(make_float2(f.x, f.y));
    __nv_bfloat162 h1 = __float22bfloat162_rn(make_float2(f.z, f.w));
    float2 l0 = make_float2(f.x - __bfloat162float(h0.x), f.y - __bfloat162float(h0.y));
    float2 l1 = make_float2(f.z - __bfloat162float(h1.x), f.w - __bfloat162float(h1.y));
    __nv_bfloat162 lo0 = __float22bfloat162_rn(l0);
    __nv_bfloat162 lo1 = __float22bfloat162_rn(l1);
    uint2 hv, lv;
    hv.x = *(uint32_t*)&h0; hv.y = *(uint32_t*)&h1;
    lv.x = *(uint32_t*)&lo0; lv.y = *(uint32_t*)&lo1;
    *(uint2*)&g_xhi[i] = hv;
    *(uint2*)&g_xlo[i] = lv;
}

// ---------------------------------------------------------------------------
// Kernel 1: mma.sync bf16-split GEMM (unchanged from R5 passing version)
// ---------------------------------------------------------------------------
#define PADROW   40
#define AHI_OFF  0
#define ALO_OFF  10240
#define BHI_OFF  20480
#define BLO_OFF  40960
#define STAGE_B  61440
#define GSMEM    (2 * STAGE_B)

__global__ __launch_bounds__(512, 1)
void gemm_xp_mma_kernel(const float* __restrict__ bh) {
    extern __shared__ __align__(16) char dsm[];
    __shared__ float bias_s[256];

    const int tid = threadIdx.x;
    const int wid = tid >> 5;
    const int lid = tid & 31;
    const int wm  = wid & 1;
    const int wn  = wid >> 1;
    const uint32_t sb = smem_u32(dsm);

    if (tid < 256) bias_s[tid] = bh[tid];

    const size_t r0 = (size_t)blockIdx.x * 128;

    auto fill = [&](int s, int kt) {
        uint32_t base = sb + s * STAGE_B;
        {
            int c = tid;
            int row = c >> 2, q = c & 3;
            size_t ga = (r0 + row) * 256 + kt + q * 8;
            uint32_t d = base + row * (PADROW * 2) + q * 16;
            cp16(d + AHI_OFF, g_xhi + ga);
            cp16(d + ALO_OFF, g_xlo + ga);
        }
#pragma unroll
        for (int i = 0; i < 2; i++) {
            int c = tid + i * 512;
            int row = c >> 2, q = c & 3;
            size_t gb = (size_t)row * 256 + kt + q * 8;
            uint32_t d = base + row * (PADROW * 2) + q * 16;
            cp16(d + BHI_OFF, g_WThi + gb);
            cp16(d + BLO_OFF, g_WTlo + gb);
        }
    };

    float acc[4][4][4];
#pragma unroll
    for (int mi = 0; mi < 4; mi++)
#pragma unroll
        for (int ni = 0; ni < 4; ni++)
#pragma unroll
            for (int e = 0; e < 4; e++) acc[mi][ni][e] = 0.f;

    fill(0, 0);
    asm volatile("cp.async.commit_group;" ::: "memory");
    fill(1, 32);
    asm volatile("cp.async.commit_group;" ::: "memory");

    const int arow  = wm * 64 + (lid & 15);
    const int acolb = (lid >> 4) * 16;
    const int bnrow = wn * 32 + (lid & 7);
    const int bkoff = ((lid >> 3) & 1) * 16;

    for (int it = 0; it < 8; it++) {
        asm volatile("cp.async.wait_group 1;" ::: "memory");
        __syncthreads();

        uint32_t As = sb + (it & 1) * STAGE_B;
        uint32_t Bs = As + BHI_OFF;

#pragma unroll
        for (int k16 = 0; k16 < 2; k16++) {
            uint32_t ahi[4][4], alo[4][4];
#pragma unroll
            for (int mi = 0; mi < 4; mi++) {
                uint32_t a = As + (arow + mi * 16) * (PADROW * 2) + k16 * 32 + acolb;
                ldsm_x4(ahi[mi], a + AHI_OFF);
                ldsm_x4(alo[mi], a + ALO_OFF);
            }
#pragma unroll
            for (int ni = 0; ni < 4; ni++) {
                uint32_t bhi[2], blo[2];
                uint32_t ba = Bs + (bnrow + ni * 8) * (PADROW * 2) + k16 * 32 + bkoff;
                ldsm_x2(bhi, ba);
                ldsm_x2(blo, ba + (BLO_OFF - BHI_OFF));
#pragma unroll
                for (int mi = 0; mi < 4; mi++) {
                    mma_bf16(acc[mi][ni], ahi[mi], bhi);
                    mma_bf16(acc[mi][ni], alo[mi], bhi);
                    mma_bf16(acc[mi][ni], ahi[mi], blo);
                }
            }
        }
        __syncthreads();
        if (it + 2 < 8) fill(it & 1, (it + 2) * 32);
        asm volatile("cp.async.commit_group;" ::: "memory");
    }

#pragma unroll
    for (int mi = 0; mi < 4; mi++) {
#pragma unroll
        for (int ni = 0; ni < 4; ni++) {
            int m = wm * 64 + mi * 16 + (lid >> 2);
            int n = wn * 32 + ni * 8 + (lid & 3) * 2;
            float b0 = bias_s[n], b1 = bias_s[n + 1];
            {
                size_t r = r0 + m;
                int t = (int)(r & 2047), b = (int)(r >> 11);
                float2 v = make_float2(acc[mi][ni][0] + b0, acc[mi][ni][1] + b1);
                *(float2*)&g_xp[((size_t)t * BATCH + b) * HID + n] = v;
            }
            {
                size_t r = r0 + m + 8;
                int t = (int)(r & 2047), b = (int)(r >> 11);
                float2 v = make_float2(acc[mi][ni][2] + b0, acc[mi][ni][3] + b1);
                *(float2*)&g_xp[((size_t)t * BATCH + b) * HID + n] = v;
            }
        }
    }
}

// ---------------------------------------------------------------------------
// Kernel 2: 16-warp, spill-free recurrence.
// 128 CTAs x 512 threads (16 warps, 4/SMSP for latency overlap).
// Warps 0-7 = k-half 0 (k in [0,128)), warps 8-15 = k-half 1 (k in [128,256)).
// Thread (half, j = tid & 255) owns column j over its 128-row k-range:
//   - k rows [kb, kb+80)    : registers (40 u64 k-pairs = 80 regs)
//   - k rows [kb+80, kb+128): smem quads (12 groups per half)
// All h loads are single-address warp broadcasts (warp is half-uniform).
// Per step: partials -> X[half][j][batch] exchange -> sync -> thread (half,j)
// finalizes (col j, batch=half): 4-way... 2-way sum + xp + tanh -> publish h
// into parity buffer -> sync. ~115 regs/thread (fits 128 cap, no spill).
// smem: W 24 groups * 4096 = 98304 | h 2par x 2b x 1KB = 4096 | X 4096.
// ---------------------------------------------------------------------------
#define R12_WREG   40                  // u64 W k-pairs in regs (80 rows)
#define R12_SGRP   12                  // smem quad groups per half (48 rows)
#define R12_WB     (24 * 4096)         // 98304
#define R12_H      R12_WB              // h: [parity][batch][256] floats
#define R12_X      (R12_WB + 4096)     // X: [half][j][batch01] floats
#define R12_SMEM   (R12_WB + 4096 + 4096)

__global__ __launch_bounds__(512, 1)
void rnn_recurrence_kernel(const float* __restrict__ W_hh) {
    extern __shared__ __align__(16) char sm[];

    const int tid  = threadIdx.x;
    const int half = tid >> 8;           // warps 0-7 -> 0, warps 8-15 -> 1
    const int j    = tid & 255;
    const int b0   = blockIdx.x * 2;
    const int kb   = half * 128;

    // --- fill W smem: group g = h*12 + u -> rows h*128 + 80 + 4u .. +3 ---
    for (int e = tid; e < 24 * 256; e += 512) {
        int g  = e >> 8;
        int jj = e & 255;
        int h = g / 12, u = g % 12;
        int row = h * 128 + 80 + 4 * u;
        float4 v;
        v.x = W_hh[(row + 0) * 256 + jj];
        v.y = W_hh[(row + 1) * 256 + jj];
        v.z = W_hh[(row + 2) * 256 + jj];
        v.w = W_hh[(row + 3) * 256 + jj];
        *(float4*)(sm + g * 4096 + jj * 16) = v;
    }

    // --- W rows [kb, kb+80) of column j -> 40 u64 k-pair registers ---
    unsigned long long wreg[R12_WREG];
#pragma unroll
    for (int r = 0; r < R12_WREG; r++)
        wreg[r] = f32x2_pack(W_hh[(kb + 2 * r) * 256 + j],
                             W_hh[(kb + 2 * r + 1) * 256 + j]);

    // --- zero h parity-0 buffer (512 floats = one per thread) ---
    ((float*)(sm + R12_H))[tid] = 0.f;
    __syncthreads();

    // finalize role: column j, batch = half
    const float* xpp = g_xp + (size_t)(b0 + half) * HID + j;
    float p = xpp[0];

    const char* wsm = sm + half * 12 * 4096 + j * 16;   // my half's smem W
    float* X = (float*)(sm + R12_X);
    float hv = 0.f;

    for (int t = 0; t < T_STEPS; t++) {
        const char* hb  = sm + R12_H + (t & 1) * 2048;
        const char* h0p = hb + kb * 4;          // h[b0], my k segment
        const char* h1p = hb + 1024 + kb * 4;   // h[b1], my k segment

        // 4 accumulator chains: (batch 0/1) x (2 pair lanes)
        unsigned long long a0x = 0, a0y = 0, a1x = 0, a1y = 0;

        int tn = (t + 1 < T_STEPS) ? (t + 1) : t;
        float pn = xpp[(size_t)tn * (BATCH * HID)];

        // register-W part: k-local [0,80), 20 h-chunks of 16B per batch
#pragma unroll
        for (int u = 0; u < 20; u++) {
            ulonglong2 h0 = *(const ulonglong2*)(h0p + u * 16);
            ulonglong2 h1 = *(const ulonglong2*)(h1p + u * 16);
            ffma2(a0x, h0.x, wreg[2 * u]);
            ffma2(a0y, h0.y, wreg[2 * u + 1]);
            ffma2(a1x, h1.x, wreg[2 * u]);
            ffma2(a1y, h1.y, wreg[2 * u + 1]);
        }
        // smem-W part: k-local [80,128), 12 quad groups
#pragma unroll
        for (int u = 0; u < R12_SGRP; u++) {
            ulonglong2 w  = *(const ulonglong2*)(wsm + u * 4096);
            ulonglong2 h0 = *(const ulonglong2*)(h0p + 320 + u * 16);
            ulonglong2 h1 = *(const ulonglong2*)(h1p + 320 + u * 16);
            ffma2(a0x, h0.x, w.x);
            ffma2(a0y, h0.y, w.y);
            ffma2(a1x, h1.x, w.x);
            ffma2(a1y, h1.y, w.y);
        }

        // collapse to 2 partial scalars (batch0, batch1)
        fadd2(a0x, a0y);
        fadd2(a1x, a1y);
        float lo, hi;
        f32x2_unpack(a0x, lo, hi); float s0 = lo + hi;
        f32x2_unpack(a1x, lo, hi); float s1 = lo + hi;

        // publish partials: X[half][j][batch] as float2
        *(float2*)&X[(half * 256 + j) * 2] = make_float2(s0, s1);
        __syncthreads();

        // finalize (col j, batch = half): sum both halves' partials + xp
        float v0 = X[j * 2 + half];                 // half0's partial, my batch
        float v1 = X[(256 + j) * 2 + half];         // half1's partial, my batch
        hv = tanhf(v0 + v1 + p);
        p = pn;

        // publish h into next parity buffer
        ((float*)(sm + R12_H + ((t + 1) & 1) * 2048))[half * 256 + j] = hv;
        __syncthreads();
    }

    g_hfinal[(size_t)(b0 + half) * HID + j] = hv;
}

// ---------------------------------------------------------------------------
// Kernel 3: classifier head (tiny)
// ---------------------------------------------------------------------------
__global__ __launch_bounds__(128)
void rnn_head_kernel(const float* __restrict__ fcw,
                     const float* __restrict__ fcb,
                     float* __restrict__ out) {
    __shared__ float hs[HID];
    __shared__ float part[8][OUT_DIM];
    const int b = blockIdx.x;
    const int tid = threadIdx.x;

    hs[tid]       = g_hfinal[(size_t)b * HID + tid];
    hs[tid + 128] = g_hfinal[(size_t)b * HID + tid + 128];
    __syncthreads();

    const int o   = tid & 15;
    const int seg = tid >> 4;
    float s = 0.f;
#pragma unroll
    for (int jj = 0; jj < 32; jj++) {
        int j = seg * 32 + jj;
        s += hs[j] * fcw[o * HID + j];
    }
    part[seg][o] = s;
    __syncthreads();
    if (tid < OUT_DIM) {
        float r = fcb[tid];
#pragma unroll
        for (int sg = 0; sg < 8; sg++) r += part[sg][tid];
        out[b * OUT_DIM + tid] = r;
    }
}

// ---------------------------------------------------------------------------
extern "C" void kernel_launch(void* const* d_in, const int* in_sizes, int n_in,
                              void* d_out, int out_size) {
    const float* x   = (const float*)d_in[0];
    const float* Wih = (const float*)d_in[1];
    const float* Whh = (const float*)d_in[2];
    const float* bh  = (const float*)d_in[3];
    const float* fcw = (const float*)d_in[4];
    const float* fcb = (const float*)d_in[5];
    float* out = (float*)d_out;

    // 0) bf16 hi/lo splits of W_ih^T and x
    prep_w_kernel<<<256, 256>>>(Wih);
    prep_x_kernel<<<131072, 256>>>(x);

    // 1) input projection GEMM on tensor cores (mma.sync) -> g_xp
    cudaFuncSetAttribute(gemm_xp_mma_kernel,
                         cudaFuncAttributeMaxDynamicSharedMemorySize, GSMEM);
    gemm_xp_mma_kernel<<<(BATCH * T_STEPS) / 128, 512, GSMEM>>>(bh);

    // 2) persistent recurrence: 16 warps, warp-uniform k-halves, no spill
    cudaFuncSetAttribute(rnn_recurrence_kernel,
                         cudaFuncAttributeMaxDynamicSharedMemorySize, R12_SMEM);
    rnn_recurrence_kernel<<<BATCH / 2, 512, R12_SMEM>>>(Whh);

    // 3) classifier head
    rnn_head_kernel<<<BATCH, 128>>>(fcw, fcb, out);
}

// round 13
// speedup vs baseline: 1.1675x; 1.1675x over previous
#include <cuda_runtime.h>
#include <cuda_bf16.h>
#include <math.h>
#include <stdint.h>

// Problem constants (fixed shapes)
#define T_STEPS 2048
#define BATCH   256
#define HID     256
#define OUT_DIM 16

// Scratch (device globals: allocation-free kernel_launch)
__device__ float g_xp[134217728];          // [T][B][H] fp32, 512 MB
__device__ float g_hfinal[BATCH * HID];
__device__ __nv_bfloat16 g_WThi[65536];    // W_ih^T hi: [n][k]
__device__ __nv_bfloat16 g_WTlo[65536];    // W_ih^T lo: [n][k]

// ---------------------------------------------------------------------------
// helpers
// ---------------------------------------------------------------------------
__device__ __forceinline__ uint32_t smem_u32(const void* p) {
    uint32_t a;
    asm("{ .reg .u64 t; cvta.to.shared.u64 t, %1; cvt.u32.u64 %0, t; }"
        : "=r"(a) : "l"(p));
    return a;
}
__device__ __forceinline__ void cp16(uint32_t dst, const void* src) {
    asm volatile("cp.async.cg.shared.global [%0], [%1], 16;"
                 :: "r"(dst), "l"(src) : "memory");
}
__device__ __forceinline__ void ldsm_x4(uint32_t* r, uint32_t addr) {
    asm volatile("ldmatrix.sync.aligned.m8n8.x4.shared.b16 {%0,%1,%2,%3}, [%4];"
                 : "=r"(r[0]), "=r"(r[1]), "=r"(r[2]), "=r"(r[3]) : "r"(addr));
}
__device__ __forceinline__ void ldsm_x2(uint32_t* r, uint32_t addr) {
    asm volatile("ldmatrix.sync.aligned.m8n8.x2.shared.b16 {%0,%1}, [%2];"
                 : "=r"(r[0]), "=r"(r[1]) : "r"(addr));
}
__device__ __forceinline__ void mma_bf16(float* c, const uint32_t* a, const uint32_t* b) {
    asm volatile(
        "mma.sync.aligned.m16n8k16.row.col.f32.bf16.bf16.f32 "
        "{%0,%1,%2,%3}, {%4,%5,%6,%7}, {%8,%9}, {%0,%1,%2,%3};"
        : "+f"(c[0]), "+f"(c[1]), "+f"(c[2]), "+f"(c[3])
        : "r"(a[0]), "r"(a[1]), "r"(a[2]), "r"(a[3]), "r"(b[0]), "r"(b[1]));
}

// f32x2 helpers (note: ffma2 = 1 issue slot, 4 datapath cycles on B300)
__device__ __forceinline__ unsigned long long f32x2_pack(float x, float y) {
    unsigned long long r;
    asm("mov.b64 %0, {%1, %2};" : "=l"(r) : "r"(__float_as_uint(x)), "r"(__float_as_uint(y)));
    return r;
}
__device__ __forceinline__ void f32x2_unpack(unsigned long long v, float& x, float& y) {
    unsigned int lo, hi;
    asm("mov.b64 {%0, %1}, %2;" : "=r"(lo), "=r"(hi) : "l"(v));
    x = __uint_as_float(lo);
    y = __uint_as_float(hi);
}
__device__ __forceinline__ void ffma2(unsigned long long& acc,
                                      unsigned long long a, unsigned long long b) {
    asm("fma.rn.f32x2 %0, %1, %2, %0;" : "+l"(acc) : "l"(a), "l"(b));
}
__device__ __forceinline__ void fadd2(unsigned long long& acc, unsigned long long b) {
    asm("add.rn.f32x2 %0, %0, %1;" : "+l"(acc) : "l"(b));
}

// ---------------------------------------------------------------------------
// Kernel 0: W_ih [k][n] -> transposed bf16 hi/lo [n][k]
// ---------------------------------------------------------------------------
__global__ __launch_bounds__(256)
void prep_w_kernel(const float* __restrict__ Wih) {
    int n = blockIdx.x;
    int k = threadIdx.x;
    float w = Wih[k * 256 + n];
    __nv_bfloat16 hi = __float2bfloat16(w);
    float lof = w - __bfloat162float(hi);
    g_WThi[n * 256 + k] = hi;
    g_WTlo[n * 256 + k] = __float2bfloat16(lof);
}

// ---------------------------------------------------------------------------
// Kernel 1: mma.sync bf16-split GEMM with in-kernel x conversion.
// xp[m][n] = sum_k x[m][k]*W[k][n] + b_h[n], m = b*2048 + t
// CTA: 128(M) x 256(N full), 512 thr = 16 warps (2 m x 8 n), warp tile 64x32.
// K: 8 chunks of 32, double-buffered. A: LDG fp32 (issued ahead of compute)
// -> register bf16 hi/lo split -> STS. B: cp.async of precomputed bf16 W^T.
// 3 MMAs per product: Ahi*Whi + Alo*Whi + Ahi*Wlo.
// ---------------------------------------------------------------------------
#define PADROW   40
#define AHI_OFF  0
#define ALO_OFF  10240
#define BHI_OFF  20480
#define BLO_OFF  40960
#define STAGE_B  61440
#define GSMEM    (2 * STAGE_B)

__global__ __launch_bounds__(512, 1)
void gemm_xp_mma_kernel(const float* __restrict__ x,
                        const float* __restrict__ bh) {
    extern __shared__ __align__(16) char dsm[];
    __shared__ float bias_s[256];

    const int tid = threadIdx.x;
    const int wid = tid >> 5;
    const int lid = tid & 31;
    const int wm  = wid & 1;
    const int wn  = wid >> 1;
    const uint32_t sb = smem_u32(dsm);

    if (tid < 256) bias_s[tid] = bh[tid];

    const size_t r0 = (size_t)blockIdx.x * 128;

    // A mapping: 128 rows x 4 q-groups (8 fp32 each) = 512 chunks, 1/thread
    const int arow_f = tid >> 2;
    const int aq_f   = tid & 3;
    const float* asrc = x + (r0 + arow_f) * 256 + aq_f * 8;

    float4 av0, av1;   // staged A fp32 (8 elems)

    auto ldA = [&](int kt) {
        av0 = *(const float4*)(asrc + kt);
        av1 = *(const float4*)(asrc + kt + 4);
    };
    auto stA = [&](int s) {
        // convert 8 fp32 -> 4 bf16x2 hi + 4 bf16x2 lo, store 16B each
        __nv_bfloat162 h0 = __float22bfloat162_rn(make_float2(av0.x, av0.y));
        __nv_bfloat162 h1 = __float22bfloat162_rn(make_float2(av0.z, av0.w));
        __nv_bfloat162 h2 = __float22bfloat162_rn(make_float2(av1.x, av1.y));
        __nv_bfloat162 h3 = __float22bfloat162_rn(make_float2(av1.z, av1.w));
        float2 l0 = make_float2(av0.x - __bfloat162float(h0.x), av0.y - __bfloat162float(h0.y));
        float2 l1 = make_float2(av0.z - __bfloat162float(h1.x), av0.w - __bfloat162float(h1.y));
        float2 l2 = make_float2(av1.x - __bfloat162float(h2.x), av1.y - __bfloat162float(h2.y));
        float2 l3 = make_float2(av1.z - __bfloat162float(h3.x), av1.w - __bfloat162float(h3.y));
        __nv_bfloat162 lo0 = __float22bfloat162_rn(l0);
        __nv_bfloat162 lo1 = __float22bfloat162_rn(l1);
        __nv_bfloat162 lo2 = __float22bfloat162_rn(l2);
        __nv_bfloat162 lo3 = __float22bfloat162_rn(l3);
        uint4 hv, lv;
        hv.x = *(uint32_t*)&h0;  hv.y = *(uint32_t*)&h1;
        hv.z = *(uint32_t*)&h2;  hv.w = *(uint32_t*)&h3;
        lv.x = *(uint32_t*)&lo0; lv.y = *(uint32_t*)&lo1;
        lv.z = *(uint32_t*)&lo2; lv.w = *(uint32_t*)&lo3;
        char* d = dsm + s * STAGE_B + arow_f * (PADROW * 2) + aq_f * 16;
        *(uint4*)(d + AHI_OFF) = hv;
        *(uint4*)(d + ALO_OFF) = lv;
    };
    auto fillW = [&](int s, int kt) {
        uint32_t base = sb + s * STAGE_B;
#pragma unroll
        for (int i = 0; i < 2; i++) {
            int c = tid + i * 512;
            int row = c >> 2, q = c & 3;
            size_t gb = (size_t)row * 256 + kt + q * 8;
            uint32_t d = base + row * (PADROW * 2) + q * 16;
            cp16(d + BHI_OFF, g_WThi + gb);
            cp16(d + BLO_OFF, g_WTlo + gb);
        }
    };

    float acc[4][4][4];
#pragma unroll
    for (int mi = 0; mi < 4; mi++)
#pragma unroll
        for (int ni = 0; ni < 4; ni++)
#pragma unroll
            for (int e = 0; e < 4; e++) acc[mi][ni][e] = 0.f;

    // prologue: fill both stages
    ldA(0);  stA(0);  fillW(0, 0);
    asm volatile("cp.async.commit_group;" ::: "memory");
    ldA(32); stA(1);  fillW(1, 32);
    asm volatile("cp.async.commit_group;" ::: "memory");

    const int arow  = wm * 64 + (lid & 15);
    const int acolb = (lid >> 4) * 16;
    const int bnrow = wn * 32 + (lid & 7);
    const int bkoff = ((lid >> 3) & 1) * 16;

    for (int it = 0; it < 8; it++) {
        asm volatile("cp.async.wait_group 1;" ::: "memory");
        __syncthreads();

        // issue next A global load BEFORE compute (hide LDG latency)
        if (it + 2 < 8) ldA((it + 2) * 32);

        uint32_t As = sb + (it & 1) * STAGE_B;
        uint32_t Bs = As + BHI_OFF;

#pragma unroll
        for (int k16 = 0; k16 < 2; k16++) {
            uint32_t ahi[4][4], alo[4][4];
#pragma unroll
            for (int mi = 0; mi < 4; mi++) {
                uint32_t a = As + (arow + mi * 16) * (PADROW * 2) + k16 * 32 + acolb;
                ldsm_x4(ahi[mi], a + AHI_OFF);
                ldsm_x4(alo[mi], a + ALO_OFF);
            }
#pragma unroll
            for (int ni = 0; ni < 4; ni++) {
                uint32_t bhi[2], blo[2];
                uint32_t ba = Bs + (bnrow + ni * 8) * (PADROW * 2) + k16 * 32 + bkoff;
                ldsm_x2(bhi, ba);
                ldsm_x2(blo, ba + (BLO_OFF - BHI_OFF));
#pragma unroll
                for (int mi = 0; mi < 4; mi++) {
                    mma_bf16(acc[mi][ni], ahi[mi], bhi);
                    mma_bf16(acc[mi][ni], alo[mi], bhi);
                    mma_bf16(acc[mi][ni], ahi[mi], blo);
                }
            }
        }
        __syncthreads();
        if (it + 2 < 8) {
            stA(it & 1);
            fillW(it & 1, (it + 2) * 32);
        }
        asm volatile("cp.async.commit_group;" ::: "memory");
    }

#pragma unroll
    for (int mi = 0; mi < 4; mi++) {
#pragma unroll
        for (int ni = 0; ni < 4; ni++) {
            int m = wm * 64 + mi * 16 + (lid >> 2);
            int n = wn * 32 + ni * 8 + (lid & 3) * 2;
            float b0 = bias_s[n], b1 = bias_s[n + 1];
            {
                size_t r = r0 + m;
                int t = (int)(r & 2047), b = (int)(r >> 11);
                float2 v = make_float2(acc[mi][ni][0] + b0, acc[mi][ni][1] + b1);
                *(float2*)&g_xp[((size_t)t * BATCH + b) * HID + n] = v;
            }
            {
                size_t r = r0 + m + 8;
                int t = (int)(r & 2047), b = (int)(r >> 11);
                float2 v = make_float2(acc[mi][ni][2] + b0, acc[mi][ni][3] + b1);
                *(float2*)&g_xp[((size_t)t * BATCH + b) * HID + n] = v;
            }
        }
    }
}

// ---------------------------------------------------------------------------
// Kernel 2: warp-uniform K-split recurrence (EXACT R8 best: 2160 cyc/step,
// within ~5% of the 2048-cyc fp32-datapath floor).
// 128 CTAs x 256 threads (8 warps). Warps 0-3 = K-half 0, warps 4-7 = K-half 1.
// Thread idx = tid & 127 owns columns jA = idx, jB = idx + 128 over its
// 128-row K-range: rows [kbase, kbase+64) in registers (u64 k-pairs),
// rows [kbase+64, kbase+128) in smem quads [group][j][4].
// All h loads are single-address warp broadcasts. Cross-half combine via
// smem float2 exchange; half0 finishes batch0, half1 finishes batch1.
// smem: W 32 groups * 4096 = 131072 | h 2*1024 @131072 | xbuf 2*1024 @133120
// ---------------------------------------------------------------------------
#define RH_OFF  131072
#define RX_OFF  133120
#define RSMEM   135168

__global__ __launch_bounds__(256, 1)
void rnn_recurrence_kernel(const float* __restrict__ W_hh) {
    extern __shared__ __align__(16) char sm[];

    const int tid  = threadIdx.x;
    const int half = tid >> 7;            // warps 0-3 -> 0, warps 4-7 -> 1
    const int idx  = tid & 127;
    const int jA   = idx;
    const int jB   = idx + 128;
    const int b0   = blockIdx.x * 2;
    const int kbase = half * 128;

    // --- fill W smem: group g = h*16 + q -> rows h*128 + 64 + 4q .. +3 ---
    for (int e = tid; e < 32 * 256; e += 256) {
        int g = e >> 8;
        int j = e & 255;
        int h = g >> 4, q = g & 15;
        int row = h * 128 + 64 + 4 * q;
        float4 v;
        v.x = W_hh[(row + 0) * 256 + j];
        v.y = W_hh[(row + 1) * 256 + j];
        v.z = W_hh[(row + 2) * 256 + j];
        v.w = W_hh[(row + 3) * 256 + j];
        *(float4*)(sm + g * 4096 + j * 16) = v;
    }

    // --- W register rows [kbase, kbase+64) for columns jA, jB (u64 k-pairs) ---
    unsigned long long wA[32], wB[32];
#pragma unroll
    for (int r = 0; r < 32; r++) {
        wA[r] = f32x2_pack(W_hh[(kbase + 2 * r) * 256 + jA],
                           W_hh[(kbase + 2 * r + 1) * 256 + jA]);
        wB[r] = f32x2_pack(W_hh[(kbase + 2 * r) * 256 + jB],
                           W_hh[(kbase + 2 * r + 1) * 256 + jB]);
    }

    // --- zero h[2][256] ---
    ((float*)(sm + RH_OFF))[tid] = 0.f;
    ((float*)(sm + RH_OFF))[tid + 256] = 0.f;
    __syncthreads();

    // xp for finish batch (= b0 + half), columns jA and jB
    const float* xpA = g_xp + (size_t)(b0 + half) * HID + jA;
    float pA = xpA[0];
    float pB = xpA[128];

    const char* hb0 = sm + RH_OFF + kbase * 4;          // h[b0], my k segment
    const char* hb1 = sm + RH_OFF + 1024 + kbase * 4;   // h[b1], my k segment
    const char* wsm = sm + half * 16 * 4096;            // my half's smem groups

    float hA = 0.f, hB = 0.f;

    for (int t = 0; t < T_STEPS; t++) {
        // 8 accumulator chains: (col A/B) x (batch 0/1) x (2 k-pair lanes)
        unsigned long long aA0x = 0, aA0y = 0, aA1x = 0, aA1y = 0;
        unsigned long long aB0x = 0, aB0y = 0, aB1x = 0, aB1y = 0;

        int tn = (t + 1 < T_STEPS) ? (t + 1) : t;
        float pAn = xpA[(size_t)tn * (BATCH * HID)];
        float pBn = xpA[(size_t)tn * (BATCH * HID) + 128];

        // register-W part: k-local [0,64), 16 h-quads
#pragma unroll
        for (int q = 0; q < 16; q++) {
            ulonglong2 h0 = *(const ulonglong2*)(hb0 + q * 16);
            ulonglong2 h1 = *(const ulonglong2*)(hb1 + q * 16);
            ffma2(aA0x, h0.x, wA[2 * q]);
            ffma2(aA0y, h0.y, wA[2 * q + 1]);
            ffma2(aA1x, h1.x, wA[2 * q]);
            ffma2(aA1y, h1.y, wA[2 * q + 1]);
            ffma2(aB0x, h0.x, wB[2 * q]);
            ffma2(aB0y, h0.y, wB[2 * q + 1]);
            ffma2(aB1x, h1.x, wB[2 * q]);
            ffma2(aB1y, h1.y, wB[2 * q + 1]);
        }
        // smem-W part: k-local [64,128), 16 h-quads
#pragma unroll
        for (int q = 0; q < 16; q++) {
            ulonglong2 wqA = *(const ulonglong2*)(wsm + q * 4096 + jA * 16);
            ulonglong2 wqB = *(const ulonglong2*)(wsm + q * 4096 + jB * 16);
            ulonglong2 h0  = *(const ulonglong2*)(hb0 + 256 + q * 16);
            ulonglong2 h1  = *(const ulonglong2*)(hb1 + 256 + q * 16);
            ffma2(aA0x, h0.x, wqA.x);
            ffma2(aA0y, h0.y, wqA.y);
            ffma2(aA1x, h1.x, wqA.x);
            ffma2(aA1y, h1.y, wqA.y);
            ffma2(aB0x, h0.x, wqB.x);
            ffma2(aB0y, h0.y, wqB.y);
            ffma2(aB1x, h1.x, wqB.x);
            ffma2(aB1y, h1.y, wqB.y);
        }

        // collapse chains -> 4 partial scalars
        fadd2(aA0x, aA0y);
        fadd2(aA1x, aA1y);
        fadd2(aB0x, aB0y);
        fadd2(aB1x, aB1y);
        float lo, hi;
        f32x2_unpack(aA0x, lo, hi); float sA0 = lo + hi;
        f32x2_unpack(aA1x, lo, hi); float sA1 = lo + hi;
        f32x2_unpack(aB0x, lo, hi); float sB0 = lo + hi;
        f32x2_unpack(aB1x, lo, hi); float sB1 = lo + hi;

        // exchange: each half publishes the OTHER batch's partials
        float2* xb = (float2*)(sm + RX_OFF + half * 1024) + idx;
        *xb = (half == 0) ? make_float2(sA1, sB1) : make_float2(sA0, sB0);
        __syncthreads();
        float2 other = *((const float2*)(sm + RX_OFF + (half ^ 1) * 1024) + idx);
        float totA = ((half == 0) ? sA0 : sA1) + other.x + pA;
        float totB = ((half == 0) ? sB0 : sB1) + other.y + pB;
        hA = tanhf(totA);
        hB = tanhf(totB);
        pA = pAn;
        pB = pBn;
        // publish h for my batch (in place: all k-loop reads finished at barrier)
        float* hrow = (float*)(sm + RH_OFF + half * 1024);
        hrow[jA] = hA;
        hrow[jB] = hB;
        __syncthreads();
    }

    g_hfinal[(size_t)(b0 + half) * HID + jA] = hA;
    g_hfinal[(size_t)(b0 + half) * HID + jB] = hB;
}

// ---------------------------------------------------------------------------
// Kernel 3: classifier head (tiny)
// ---------------------------------------------------------------------------
__global__ __launch_bounds__(128)
void rnn_head_kernel(const float* __restrict__ fcw,
                     const float* __restrict__ fcb,
                     float* __restrict__ out) {
    __shared__ float hs[HID];
    __shared__ float part[8][OUT_DIM];
    const int b = blockIdx.x;
    const int tid = threadIdx.x;

    hs[tid]       = g_hfinal[(size_t)b * HID + tid];
    hs[tid + 128] = g_hfinal[(size_t)b * HID + tid + 128];
    __syncthreads();

    const int o   = tid & 15;
    const int seg = tid >> 4;
    float s = 0.f;
#pragma unroll
    for (int jj = 0; jj < 32; jj++) {
        int j = seg * 32 + jj;
        s += hs[j] * fcw[o * HID + j];
    }
    part[seg][o] = s;
    __syncthreads();
    if (tid < OUT_DIM) {
        float r = fcb[tid];
#pragma unroll
        for (int sg = 0; sg < 8; sg++) r += part[sg][tid];
        out[b * OUT_DIM + tid] = r;
    }
}

// ---------------------------------------------------------------------------
extern "C" void kernel_launch(void* const* d_in, const int* in_sizes, int n_in,
                              void* d_out, int out_size) {
    const float* x   = (const float*)d_in[0];
    const float* Wih = (const float*)d_in[1];
    const float* Whh = (const float*)d_in[2];
    const float* bh  = (const float*)d_in[3];
    const float* fcw = (const float*)d_in[4];
    const float* fcb = (const float*)d_in[5];
    float* out = (float*)d_out;

    // 0) bf16 hi/lo split of W_ih^T only (x converted inside the GEMM)
    prep_w_kernel<<<256, 256>>>(Wih);

    // 1) input projection GEMM on tensor cores (mma.sync) -> g_xp
    cudaFuncSetAttribute(gemm_xp_mma_kernel,
                         cudaFuncAttributeMaxDynamicSharedMemorySize, GSMEM);
    gemm_xp_mma_kernel<<<(BATCH * T_STEPS) / 128, 512, GSMEM>>>(x, bh);

    // 2) persistent recurrence (R8-best: warp-uniform K-split, 2 cols/thread)
    cudaFuncSetAttribute(rnn_recurrence_kernel,
                         cudaFuncAttributeMaxDynamicSharedMemorySize, RSMEM);
    rnn_recurrence_kernel<<<BATCH / 2, 256, RSMEM>>>(Whh);

    // 3) classifier head
    rnn_head_kernel<<<BATCH, 128>>>(fcw, fcb, out);
}

// round 14
// speedup vs baseline: 1.2952x; 1.1094x over previous
#include <cuda_runtime.h>
#include <cuda_bf16.h>
#include <math.h>
#include <stdint.h>

// Problem constants (fixed shapes)
#define T_STEPS 2048
#define BATCH   256
#define HID     256
#define OUT_DIM 16

// Scratch (device globals: allocation-free kernel_launch)
__device__ float g_xp[134217728];          // [T][B][H] fp32, 512 MB
__device__ float g_hfinal[BATCH * HID];
__device__ __nv_bfloat16 g_WThi[65536];    // W_ih^T hi: [n][k]
__device__ __nv_bfloat16 g_WTlo[65536];    // W_ih^T lo: [n][k]

// ---------------------------------------------------------------------------
// helpers
// ---------------------------------------------------------------------------
__device__ __forceinline__ uint32_t smem_u32(const void* p) {
    uint32_t a;
    asm("{ .reg .u64 t; cvta.to.shared.u64 t, %1; cvt.u32.u64 %0, t; }"
        : "=r"(a) : "l"(p));
    return a;
}
__device__ __forceinline__ void cp16(uint32_t dst, const void* src) {
    asm volatile("cp.async.cg.shared.global [%0], [%1], 16;"
                 :: "r"(dst), "l"(src) : "memory");
}
__device__ __forceinline__ void ldsm_x4(uint32_t* r, uint32_t addr) {
    asm volatile("ldmatrix.sync.aligned.m8n8.x4.shared.b16 {%0,%1,%2,%3}, [%4];"
                 : "=r"(r[0]), "=r"(r[1]), "=r"(r[2]), "=r"(r[3]) : "r"(addr));
}
__device__ __forceinline__ void ldsm_x2(uint32_t* r, uint32_t addr) {
    asm volatile("ldmatrix.sync.aligned.m8n8.x2.shared.b16 {%0,%1}, [%2];"
                 : "=r"(r[0]), "=r"(r[1]) : "r"(addr));
}
__device__ __forceinline__ void mma_bf16(float* c, const uint32_t* a, const uint32_t* b) {
    asm volatile(
        "mma.sync.aligned.m16n8k16.row.col.f32.bf16.bf16.f32 "
        "{%0,%1,%2,%3}, {%4,%5,%6,%7}, {%8,%9}, {%0,%1,%2,%3};"
        : "+f"(c[0]), "+f"(c[1]), "+f"(c[2]), "+f"(c[3])
        : "r"(a[0]), "r"(a[1]), "r"(a[2]), "r"(a[3]), "r"(b[0]), "r"(b[1]));
}

// f32x2 helpers (note: ffma2 = 1 issue slot, 4 datapath cycles on B300)
__device__ __forceinline__ unsigned long long f32x2_pack(float x, float y) {
    unsigned long long r;
    asm("mov.b64 %0, {%1, %2};" : "=l"(r) : "r"(__float_as_uint(x)), "r"(__float_as_uint(y)));
    return r;
}
__device__ __forceinline__ void f32x2_unpack(unsigned long long v, float& x, float& y) {
    unsigned int lo, hi;
    asm("mov.b64 {%0, %1}, %2;" : "=r"(lo), "=r"(hi) : "l"(v));
    x = __uint_as_float(lo);
    y = __uint_as_float(hi);
}
__device__ __forceinline__ void ffma2(unsigned long long& acc,
                                      unsigned long long a, unsigned long long b) {
    asm("fma.rn.f32x2 %0, %1, %2, %0;" : "+l"(acc) : "l"(a), "l"(b));
}
__device__ __forceinline__ void fadd2(unsigned long long& acc, unsigned long long b) {
    asm("add.rn.f32x2 %0, %0, %1;" : "+l"(acc) : "l"(b));
}

// fast tanh: 1 - 2/(e^{2x}+1); clamped (tanh(15) == 1.0f in fp32 anyway).
// ~5 instructions (2 MUFU) vs ~30 for libm tanhf. rel err ~1e-6.
__device__ __forceinline__ float fast_tanh(float x) {
    float xc = fminf(fmaxf(x, -15.f), 15.f);
    float e  = __expf(2.f * xc);
    return 1.f - __fdividef(2.f, e + 1.f);
}

// ---------------------------------------------------------------------------
// Kernel 0: W_ih [k][n] -> transposed bf16 hi/lo [n][k]
// ---------------------------------------------------------------------------
__global__ __launch_bounds__(256)
void prep_w_kernel(const float* __restrict__ Wih) {
    int n = blockIdx.x;
    int k = threadIdx.x;
    float w = Wih[k * 256 + n];
    __nv_bfloat16 hi = __float2bfloat16(w);
    float lof = w - __bfloat162float(hi);
    g_WThi[n * 256 + k] = hi;
    g_WTlo[n * 256 + k] = __float2bfloat16(lof);
}

// ---------------------------------------------------------------------------
// Kernel 1: mma.sync bf16-split GEMM with in-kernel x conversion and
// smem-staged coalesced epilogue.
// xp[m][n] = sum_k x[m][k]*W[k][n] + b_h[n], m = b*2048 + t
// CTA: 128(M) x 256(N full), 512 thr = 16 warps (2 m x 8 n), warp tile 64x32.
// ---------------------------------------------------------------------------
#define PADROW   40
#define AHI_OFF  0
#define ALO_OFF  10240
#define BHI_OFF  20480
#define BLO_OFF  40960
#define STAGE_B  61440
#define GSMEM    (2 * STAGE_B)

__global__ __launch_bounds__(512, 1)
void gemm_xp_mma_kernel(const float* __restrict__ x,
                        const float* __restrict__ bh) {
    extern __shared__ __align__(16) char dsm[];
    __shared__ float bias_s[256];

    const int tid = threadIdx.x;
    const int wid = tid >> 5;
    const int lid = tid & 31;
    const int wm  = wid & 1;
    const int wn  = wid >> 1;
    const uint32_t sb = smem_u32(dsm);

    if (tid < 256) bias_s[tid] = bh[tid];

    const size_t r0 = (size_t)blockIdx.x * 128;

    // A mapping: 128 rows x 4 q-groups (8 fp32 each) = 512 chunks, 1/thread
    const int arow_f = tid >> 2;
    const int aq_f   = tid & 3;
    const float* asrc = x + (r0 + arow_f) * 256 + aq_f * 8;

    float4 av0, av1;   // staged A fp32 (8 elems)

    auto ldA = [&](int kt) {
        av0 = *(const float4*)(asrc + kt);
        av1 = *(const float4*)(asrc + kt + 4);
    };
    auto stA = [&](int s) {
        __nv_bfloat162 h0 = __float22bfloat162_rn(make_float2(av0.x, av0.y));
        __nv_bfloat162 h1 = __float22bfloat162_rn(make_float2(av0.z, av0.w));
        __nv_bfloat162 h2 = __float22bfloat162_rn(make_float2(av1.x, av1.y));
        __nv_bfloat162 h3 = __float22bfloat162_rn(make_float2(av1.z, av1.w));
        float2 l0 = make_float2(av0.x - __bfloat162float(h0.x), av0.y - __bfloat162float(h0.y));
        float2 l1 = make_float2(av0.z - __bfloat162float(h1.x), av0.w - __bfloat162float(h1.y));
        float2 l2 = make_float2(av1.x - __bfloat162float(h2.x), av1.y - __bfloat162float(h2.y));
        float2 l3 = make_float2(av1.z - __bfloat162float(h3.x), av1.w - __bfloat162float(h3.y));
        __nv_bfloat162 lo0 = __float22bfloat162_rn(l0);
        __nv_bfloat162 lo1 = __float22bfloat162_rn(l1);
        __nv_bfloat162 lo2 = __float22bfloat162_rn(l2);
        __nv_bfloat162 lo3 = __float22bfloat162_rn(l3);
        uint4 hv, lv;
        hv.x = *(uint32_t*)&h0;  hv.y = *(uint32_t*)&h1;
        hv.z = *(uint32_t*)&h2;  hv.w = *(uint32_t*)&h3;
        lv.x = *(uint32_t*)&lo0; lv.y = *(uint32_t*)&lo1;
        lv.z = *(uint32_t*)&lo2; lv.w = *(uint32_t*)&lo3;
        char* d = dsm + s * STAGE_B + arow_f * (PADROW * 2) + aq_f * 16;
        *(uint4*)(d + AHI_OFF) = hv;
        *(uint4*)(d + ALO_OFF) = lv;
    };
    auto fillW = [&](int s, int kt) {
        uint32_t base = sb + s * STAGE_B;
#pragma unroll
        for (int i = 0; i < 2; i++) {
            int c = tid + i * 512;
            int row = c >> 2, q = c & 3;
            size_t gb = (size_t)row * 256 + kt + q * 8;
            uint32_t d = base + row * (PADROW * 2) + q * 16;
            cp16(d + BHI_OFF, g_WThi + gb);
            cp16(d + BLO_OFF, g_WTlo + gb);
        }
    };

    float acc[4][4][4];
#pragma unroll
    for (int mi = 0; mi < 4; mi++)
#pragma unroll
        for (int ni = 0; ni < 4; ni++)
#pragma unroll
            for (int e = 0; e < 4; e++) acc[mi][ni][e] = 0.f;

    // prologue: fill both stages
    ldA(0);  stA(0);  fillW(0, 0);
    asm volatile("cp.async.commit_group;" ::: "memory");
    ldA(32); stA(1);  fillW(1, 32);
    asm volatile("cp.async.commit_group;" ::: "memory");

    const int arow  = wm * 64 + (lid & 15);
    const int acolb = (lid >> 4) * 16;
    const int bnrow = wn * 32 + (lid & 7);
    const int bkoff = ((lid >> 3) & 1) * 16;

    for (int it = 0; it < 8; it++) {
        asm volatile("cp.async.wait_group 1;" ::: "memory");
        __syncthreads();

        if (it + 2 < 8) ldA((it + 2) * 32);

        uint32_t As = sb + (it & 1) * STAGE_B;
        uint32_t Bs = As + BHI_OFF;

#pragma unroll
        for (int k16 = 0; k16 < 2; k16++) {
            uint32_t ahi[4][4], alo[4][4];
#pragma unroll
            for (int mi = 0; mi < 4; mi++) {
                uint32_t a = As + (arow + mi * 16) * (PADROW * 2) + k16 * 32 + acolb;
                ldsm_x4(ahi[mi], a + AHI_OFF);
                ldsm_x4(alo[mi], a + ALO_OFF);
            }
#pragma unroll
            for (int ni = 0; ni < 4; ni++) {
                uint32_t bhi[2], blo[2];
                uint32_t ba = Bs + (bnrow + ni * 8) * (PADROW * 2) + k16 * 32 + bkoff;
                ldsm_x2(bhi, ba);
                ldsm_x2(blo, ba + (BLO_OFF - BHI_OFF));
#pragma unroll
                for (int mi = 0; mi < 4; mi++) {
                    mma_bf16(acc[mi][ni], ahi[mi], bhi);
                    mma_bf16(acc[mi][ni], alo[mi], bhi);
                    mma_bf16(acc[mi][ni], ahi[mi], blo);
                }
            }
        }
        __syncthreads();
        if (it + 2 < 8) {
            stA(it & 1);
            fillW(it & 1, (it + 2) * 32);
        }
        asm volatile("cp.async.commit_group;" ::: "memory");
    }

    // ---- epilogue: stage 32-row chunks in smem, write g_xp coalesced ----
    asm volatile("cp.async.wait_group 0;" ::: "memory");
    __syncthreads();
    float* stage = (float*)dsm;   // 32*256 floats = 32 KB
#pragma unroll
    for (int c = 0; c < 4; c++) {
        // rows [32c, 32c+32): owned by warps with wm == c>>1, mi = (c&1)*2 + {0,1}
        if (wm == (c >> 1)) {
#pragma unroll
            for (int mm = 0; mm < 2; mm++) {
                int mi = (c & 1) * 2 + mm;
                int lrow = mi * 16 + (lid >> 2) - (c & 1) * 32;   // 0..23 (+8 pair)
#pragma unroll
                for (int ni = 0; ni < 4; ni++) {
                    int n = wn * 32 + ni * 8 + (lid & 3) * 2;
                    float b0 = bias_s[n], b1 = bias_s[n + 1];
                    *(float2*)&stage[lrow * 256 + n] =
                        make_float2(acc[mi][ni][0] + b0, acc[mi][ni][1] + b1);
                    *(float2*)&stage[(lrow + 8) * 256 + n] =
                        make_float2(acc[mi][ni][2] + b0, acc[mi][ni][3] + b1);
                }
            }
        }
        __syncthreads();
        // coalesced write: 512 threads cover 32 rows x 256 floats
        {
            int lrow = tid >> 4;             // 0..31
            int col  = (tid & 15) * 16;      // 16 floats per thread
            size_t r = r0 + c * 32 + lrow;
            int t = (int)(r & 2047), b = (int)(r >> 11);
            float* dst = &g_xp[((size_t)t * BATCH + b) * HID + col];
            const float4* srcp = (const float4*)&stage[lrow * 256 + col];
#pragma unroll
            for (int q = 0; q < 4; q++) ((float4*)dst)[q] = srcp[q];
        }
        __syncthreads();
    }
}

// ---------------------------------------------------------------------------
// Kernel 2: warp-uniform K-split recurrence (R8/R13 best structure; only
// change: fast_tanh instead of tanhf).
// 128 CTAs x 256 threads (8 warps). Warps 0-3 = K-half 0, warps 4-7 = K-half 1.
// Thread idx = tid & 127 owns columns jA = idx, jB = idx + 128 over its
// 128-row K-range: rows [kbase, kbase+64) in registers (u64 k-pairs),
// rows [kbase+64, kbase+128) in smem quads [group][j][4].
// smem: W 32 groups * 4096 = 131072 | h 2*1024 @131072 | xbuf 2*1024 @133120
// ---------------------------------------------------------------------------
#define RH_OFF  131072
#define RX_OFF  133120
#define RSMEM   135168

__global__ __launch_bounds__(256, 1)
void rnn_recurrence_kernel(const float* __restrict__ W_hh) {
    extern __shared__ __align__(16) char sm[];

    const int tid  = threadIdx.x;
    const int half = tid >> 7;            // warps 0-3 -> 0, warps 4-7 -> 1
    const int idx  = tid & 127;
    const int jA   = idx;
    const int jB   = idx + 128;
    const int b0   = blockIdx.x * 2;
    const int kbase = half * 128;

    // --- fill W smem: group g = h*16 + q -> rows h*128 + 64 + 4q .. +3 ---
    for (int e = tid; e < 32 * 256; e += 256) {
        int g = e >> 8;
        int j = e & 255;
        int h = g >> 4, q = g & 15;
        int row = h * 128 + 64 + 4 * q;
        float4 v;
        v.x = W_hh[(row + 0) * 256 + j];
        v.y = W_hh[(row + 1) * 256 + j];
        v.z = W_hh[(row + 2) * 256 + j];
        v.w = W_hh[(row + 3) * 256 + j];
        *(float4*)(sm + g * 4096 + j * 16) = v;
    }

    // --- W register rows [kbase, kbase+64) for columns jA, jB (u64 k-pairs) ---
    unsigned long long wA[32], wB[32];
#pragma unroll
    for (int r = 0; r < 32; r++) {
        wA[r] = f32x2_pack(W_hh[(kbase + 2 * r) * 256 + jA],
                           W_hh[(kbase + 2 * r + 1) * 256 + jA]);
        wB[r] = f32x2_pack(W_hh[(kbase + 2 * r) * 256 + jB],
                           W_hh[(kbase + 2 * r + 1) * 256 + jB]);
    }

    // --- zero h[2][256] ---
    ((float*)(sm + RH_OFF))[tid] = 0.f;
    ((float*)(sm + RH_OFF))[tid + 256] = 0.f;
    __syncthreads();

    // xp for finish batch (= b0 + half), columns jA and jB
    const float* xpA = g_xp + (size_t)(b0 + half) * HID + jA;
    float pA = xpA[0];
    float pB = xpA[128];

    const char* hb0 = sm + RH_OFF + kbase * 4;          // h[b0], my k segment
    const char* hb1 = sm + RH_OFF + 1024 + kbase * 4;   // h[b1], my k segment
    const char* wsm = sm + half * 16 * 4096;            // my half's smem groups

    float hA = 0.f, hB = 0.f;

    for (int t = 0; t < T_STEPS; t++) {
        // 8 accumulator chains: (col A/B) x (batch 0/1) x (2 k-pair lanes)
        unsigned long long aA0x = 0, aA0y = 0, aA1x = 0, aA1y = 0;
        unsigned long long aB0x = 0, aB0y = 0, aB1x = 0, aB1y = 0;

        int tn = (t + 1 < T_STEPS) ? (t + 1) : t;
        float pAn = xpA[(size_t)tn * (BATCH * HID)];
        float pBn = xpA[(size_t)tn * (BATCH * HID) + 128];

        // register-W part: k-local [0,64), 16 h-quads
#pragma unroll
        for (int q = 0; q < 16; q++) {
            ulonglong2 h0 = *(const ulonglong2*)(hb0 + q * 16);
            ulonglong2 h1 = *(const ulonglong2*)(hb1 + q * 16);
            ffma2(aA0x, h0.x, wA[2 * q]);
            ffma2(aA0y, h0.y, wA[2 * q + 1]);
            ffma2(aA1x, h1.x, wA[2 * q]);
            ffma2(aA1y, h1.y, wA[2 * q + 1]);
            ffma2(aB0x, h0.x, wB[2 * q]);
            ffma2(aB0y, h0.y, wB[2 * q + 1]);
            ffma2(aB1x, h1.x, wB[2 * q]);
            ffma2(aB1y, h1.y, wB[2 * q + 1]);
        }
        // smem-W part: k-local [64,128), 16 h-quads
#pragma unroll
        for (int q = 0; q < 16; q++) {
            ulonglong2 wqA = *(const ulonglong2*)(wsm + q * 4096 + jA * 16);
            ulonglong2 wqB = *(const ulonglong2*)(wsm + q * 4096 + jB * 16);
            ulonglong2 h0  = *(const ulonglong2*)(hb0 + 256 + q * 16);
            ulonglong2 h1  = *(const ulonglong2*)(hb1 + 256 + q * 16);
            ffma2(aA0x, h0.x, wqA.x);
            ffma2(aA0y, h0.y, wqA.y);
            ffma2(aA1x, h1.x, wqA.x);
            ffma2(aA1y, h1.y, wqA.y);
            ffma2(aB0x, h0.x, wqB.x);
            ffma2(aB0y, h0.y, wqB.y);
            ffma2(aB1x, h1.x, wqB.x);
            ffma2(aB1y, h1.y, wqB.y);
        }

        // collapse chains -> 4 partial scalars
        fadd2(aA0x, aA0y);
        fadd2(aA1x, aA1y);
        fadd2(aB0x, aB0y);
        fadd2(aB1x, aB1y);
        float lo, hi;
        f32x2_unpack(aA0x, lo, hi); float sA0 = lo + hi;
        f32x2_unpack(aA1x, lo, hi); float sA1 = lo + hi;
        f32x2_unpack(aB0x, lo, hi); float sB0 = lo + hi;
        f32x2_unpack(aB1x, lo, hi); float sB1 = lo + hi;

        // exchange: each half publishes the OTHER batch's partials
        float2* xb = (float2*)(sm + RX_OFF + half * 1024) + idx;
        *xb = (half == 0) ? make_float2(sA1, sB1) : make_float2(sA0, sB0);
        __syncthreads();
        float2 other = *((const float2*)(sm + RX_OFF + (half ^ 1) * 1024) + idx);
        float totA = ((half == 0) ? sA0 : sA1) + other.x + pA;
        float totB = ((half == 0) ? sB0 : sB1) + other.y + pB;
        hA = fast_tanh(totA);
        hB = fast_tanh(totB);
        pA = pAn;
        pB = pBn;
        // publish h for my batch (in place: all k-loop reads finished at barrier)
        float* hrow = (float*)(sm + RH_OFF + half * 1024);
        hrow[jA] = hA;
        hrow[jB] = hB;
        __syncthreads();
    }

    g_hfinal[(size_t)(b0 + half) * HID + jA] = hA;
    g_hfinal[(size_t)(b0 + half) * HID + jB] = hB;
}

// ---------------------------------------------------------------------------
// Kernel 3: classifier head (tiny)
// ---------------------------------------------------------------------------
__global__ __launch_bounds__(128)
void rnn_head_kernel(const float* __restrict__ fcw,
                     const float* __restrict__ fcb,
                     float* __restrict__ out) {
    __shared__ float hs[HID];
    __shared__ float part[8][OUT_DIM];
    const int b = blockIdx.x;
    const int tid = threadIdx.x;

    hs[tid]       = g_hfinal[(size_t)b * HID + tid];
    hs[tid + 128] = g_hfinal[(size_t)b * HID + tid + 128];
    __syncthreads();

    const int o   = tid & 15;
    const int seg = tid >> 4;
    float s = 0.f;
#pragma unroll
    for (int jj = 0; jj < 32; jj++) {
        int j = seg * 32 + jj;
        s += hs[j] * fcw[o * HID + j];
    }
    part[seg][o] = s;
    __syncthreads();
    if (tid < OUT_DIM) {
        float r = fcb[tid];
#pragma unroll
        for (int sg = 0; sg < 8; sg++) r += part[sg][tid];
        out[b * OUT_DIM + tid] = r;
    }
}

// ---------------------------------------------------------------------------
extern "C" void kernel_launch(void* const* d_in, const int* in_sizes, int n_in,
                              void* d_out, int out_size) {
    const float* x   = (const float*)d_in[0];
    const float* Wih = (const float*)d_in[1];
    const float* Whh = (const float*)d_in[2];
    const float* bh  = (const float*)d_in[3];
    const float* fcw = (const float*)d_in[4];
    const float* fcb = (const float*)d_in[5];
    float* out = (float*)d_out;

    // 0) bf16 hi/lo split of W_ih^T only (x converted inside the GEMM)
    prep_w_kernel<<<256, 256>>>(Wih);

    // 1) input projection GEMM on tensor cores (mma.sync) -> g_xp
    cudaFuncSetAttribute(gemm_xp_mma_kernel,
                         cudaFuncAttributeMaxDynamicSharedMemorySize, GSMEM);
    gemm_xp_mma_kernel<<<(BATCH * T_STEPS) / 128, 512, GSMEM>>>(x, bh);

    // 2) persistent recurrence (R8-best + fast_tanh)
    cudaFuncSetAttribute(rnn_recurrence_kernel,
                         cudaFuncAttributeMaxDynamicSharedMemorySize, RSMEM);
    rnn_recurrence_kernel<<<BATCH / 2, 256, RSMEM>>>(Whh);

    // 3) classifier head
    rnn_head_kernel<<<BATCH, 128>>>(fcw, fcb, out);
}

// round 15
// speedup vs baseline: 1.2994x; 1.0032x over previous
#include <cuda_runtime.h>
#include <cuda_bf16.h>
#include <math.h>
#include <stdint.h>

// Problem constants (fixed shapes)
#define T_STEPS 2048
#define BATCH   256
#define HID     256
#define OUT_DIM 16

// Scratch (device globals: allocation-free kernel_launch)
__device__ float g_xp[134217728];          // [T][B][H] fp32, 512 MB
__device__ float g_hfinal[BATCH * HID];
__device__ __nv_bfloat16 g_WThi[65536];    // W_ih^T hi: [n][k]
__device__ __nv_bfloat16 g_WTlo[65536];    // W_ih^T lo: [n][k]

// ---------------------------------------------------------------------------
// helpers
// ---------------------------------------------------------------------------
__device__ __forceinline__ uint32_t smem_u32(const void* p) {
    uint32_t a;
    asm("{ .reg .u64 t; cvta.to.shared.u64 t, %1; cvt.u32.u64 %0, t; }"
        : "=r"(a) : "l"(p));
    return a;
}
__device__ __forceinline__ void cp16(uint32_t dst, const void* src) {
    asm volatile("cp.async.cg.shared.global [%0], [%1], 16;"
                 :: "r"(dst), "l"(src) : "memory");
}
__device__ __forceinline__ void ldsm_x4(uint32_t* r, uint32_t addr) {
    asm volatile("ldmatrix.sync.aligned.m8n8.x4.shared.b16 {%0,%1,%2,%3}, [%4];"
                 : "=r"(r[0]), "=r"(r[1]), "=r"(r[2]), "=r"(r[3]) : "r"(addr));
}
__device__ __forceinline__ void ldsm_x2(uint32_t* r, uint32_t addr) {
    asm volatile("ldmatrix.sync.aligned.m8n8.x2.shared.b16 {%0,%1}, [%2];"
                 : "=r"(r[0]), "=r"(r[1]) : "r"(addr));
}
__device__ __forceinline__ void mma_bf16(float* c, const uint32_t* a, const uint32_t* b) {
    asm volatile(
        "mma.sync.aligned.m16n8k16.row.col.f32.bf16.bf16.f32 "
        "{%0,%1,%2,%3}, {%4,%5,%6,%7}, {%8,%9}, {%0,%1,%2,%3};"
        : "+f"(c[0]), "+f"(c[1]), "+f"(c[2]), "+f"(c[3])
        : "r"(a[0]), "r"(a[1]), "r"(a[2]), "r"(a[3]), "r"(b[0]), "r"(b[1]));
}

// f32x2 helpers (note: ffma2 = 1 issue slot, 4 datapath cycles on B300)
__device__ __forceinline__ unsigned long long f32x2_pack(float x, float y) {
    unsigned long long r;
    asm("mov.b64 %0, {%1, %2};" : "=l"(r) : "r"(__float_as_uint(x)), "r"(__float_as_uint(y)));
    return r;
}
__device__ __forceinline__ void f32x2_unpack(unsigned long long v, float& x, float& y) {
    unsigned int lo, hi;
    asm("mov.b64 {%0, %1}, %2;" : "=r"(lo), "=r"(hi) : "l"(v));
    x = __uint_as_float(lo);
    y = __uint_as_float(hi);
}
__device__ __forceinline__ void ffma2(unsigned long long& acc,
                                      unsigned long long a, unsigned long long b) {
    asm("fma.rn.f32x2 %0, %1, %2, %0;" : "+l"(acc) : "l"(a), "l"(b));
}
__device__ __forceinline__ void fadd2(unsigned long long& acc, unsigned long long b) {
    asm("add.rn.f32x2 %0, %0, %1;" : "+l"(acc) : "l"(b));
}

// fast tanh: 1 - 2/(e^{2x}+1); clamped. ~5 instr (2 MUFU), rel err ~1e-6.
__device__ __forceinline__ float fast_tanh(float x) {
    float xc = fminf(fmaxf(x, -15.f), 15.f);
    float e  = __expf(2.f * xc);
    return 1.f - __fdividef(2.f, e + 1.f);
}

// ---------------------------------------------------------------------------
// Kernel 0: W_ih [k][n] -> transposed bf16 hi/lo [n][k]
// ---------------------------------------------------------------------------
__global__ __launch_bounds__(256)
void prep_w_kernel(const float* __restrict__ Wih) {
    int n = blockIdx.x;
    int k = threadIdx.x;
    float w = Wih[k * 256 + n];
    __nv_bfloat16 hi = __float2bfloat16(w);
    float lof = w - __bfloat162float(hi);
    g_WThi[n * 256 + k] = hi;
    g_WTlo[n * 256 + k] = __float2bfloat16(lof);
}

// ---------------------------------------------------------------------------
// Kernel 1: mma.sync bf16-split GEMM, 3-stage pipeline, 1 sync/iter.
// xp[m][n] = sum_k x[m][k]*W[k][n] + b_h[n], m = b*2048 + t
// CTA: 128(M) x 256(N full), 512 thr = 16 warps (2 m x 8 n), warp tile 64x32.
// Per iter: [ldA + fillW + commit] -> compute(stage it%3) -> stA((it+2)%3).
// Stage (it+2)%3 == (it-1)%3 was retired by this iter's top syncthreads.
// ---------------------------------------------------------------------------
#define PADROW   40
#define AHI_OFF  0
#define ALO_OFF  10240
#define BHI_OFF  20480
#define BLO_OFF  40960
#define STAGE_B  61440
#define GSMEM    (3 * STAGE_B)

__global__ __launch_bounds__(512, 1)
void gemm_xp_mma_kernel(const float* __restrict__ x,
                        const float* __restrict__ bh) {
    extern __shared__ __align__(16) char dsm[];
    __shared__ float bias_s[256];

    const int tid = threadIdx.x;
    const int wid = tid >> 5;
    const int lid = tid & 31;
    const int wm  = wid & 1;
    const int wn  = wid >> 1;
    const uint32_t sb = smem_u32(dsm);

    if (tid < 256) bias_s[tid] = bh[tid];

    const size_t r0 = (size_t)blockIdx.x * 128;

    // A mapping: 128 rows x 4 q-groups (8 fp32 each) = 512 chunks, 1/thread
    const int arow_f = tid >> 2;
    const int aq_f   = tid & 3;
    const float* asrc = x + (r0 + arow_f) * 256 + aq_f * 8;

    float4 av0, av1;   // staged A fp32 (8 elems)

    auto ldA = [&](int kt) {
        av0 = *(const float4*)(asrc + kt);
        av1 = *(const float4*)(asrc + kt + 4);
    };
    auto stA = [&](int s) {
        __nv_bfloat162 h0 = __float22bfloat162_rn(make_float2(av0.x, av0.y));
        __nv_bfloat162 h1 = __float22bfloat162_rn(make_float2(av0.z, av0.w));
        __nv_bfloat162 h2 = __float22bfloat162_rn(make_float2(av1.x, av1.y));
        __nv_bfloat162 h3 = __float22bfloat162_rn(make_float2(av1.z, av1.w));
        float2 l0 = make_float2(av0.x - __bfloat162float(h0.x), av0.y - __bfloat162float(h0.y));
        float2 l1 = make_float2(av0.z - __bfloat162float(h1.x), av0.w - __bfloat162float(h1.y));
        float2 l2 = make_float2(av1.x - __bfloat162float(h2.x), av1.y - __bfloat162float(h2.y));
        float2 l3 = make_float2(av1.z - __bfloat162float(h3.x), av1.w - __bfloat162float(h3.y));
        __nv_bfloat162 lo0 = __float22bfloat162_rn(l0);
        __nv_bfloat162 lo1 = __float22bfloat162_rn(l1);
        __nv_bfloat162 lo2 = __float22bfloat162_rn(l2);
        __nv_bfloat162 lo3 = __float22bfloat162_rn(l3);
        uint4 hv, lv;
        hv.x = *(uint32_t*)&h0;  hv.y = *(uint32_t*)&h1;
        hv.z = *(uint32_t*)&h2;  hv.w = *(uint32_t*)&h3;
        lv.x = *(uint32_t*)&lo0; lv.y = *(uint32_t*)&lo1;
        lv.z = *(uint32_t*)&lo2; lv.w = *(uint32_t*)&lo3;
        char* d = dsm + s * STAGE_B + arow_f * (PADROW * 2) + aq_f * 16;
        *(uint4*)(d + AHI_OFF) = hv;
        *(uint4*)(d + ALO_OFF) = lv;
    };
    auto fillW = [&](int s, int kt) {
        uint32_t base = sb + s * STAGE_B;
#pragma unroll
        for (int i = 0; i < 2; i++) {
            int c = tid + i * 512;
            int row = c >> 2, q = c & 3;
            size_t gb = (size_t)row * 256 + kt + q * 8;
            uint32_t d = base + row * (PADROW * 2) + q * 16;
            cp16(d + BHI_OFF, g_WThi + gb);
            cp16(d + BLO_OFF, g_WTlo + gb);
        }
    };

    float acc[4][4][4];
#pragma unroll
    for (int mi = 0; mi < 4; mi++)
#pragma unroll
        for (int ni = 0; ni < 4; ni++)
#pragma unroll
            for (int e = 0; e < 4; e++) acc[mi][ni][e] = 0.f;

    // prologue: stages 0 and 1
    ldA(0);  fillW(0, 0);
    asm volatile("cp.async.commit_group;" ::: "memory");
    stA(0);
    ldA(32); fillW(1, 32);
    asm volatile("cp.async.commit_group;" ::: "memory");
    stA(1);

    const int arow  = wm * 64 + (lid & 15);
    const int acolb = (lid >> 4) * 16;
    const int bnrow = wn * 32 + (lid & 7);
    const int bkoff = ((lid >> 3) & 1) * 16;

    for (int it = 0; it < 8; it++) {
        asm volatile("cp.async.wait_group 1;" ::: "memory");
        __syncthreads();   // stage it%3 ready for all; stage (it+2)%3 retired

        const int sNext = (it + 2) % 3;
        if (it + 2 < 8) {
            ldA((it + 2) * 32);          // LDG early (latency hidden by compute)
            fillW(sNext, (it + 2) * 32); // cp.async into free stage
        }
        asm volatile("cp.async.commit_group;" ::: "memory");

        uint32_t As = sb + (it % 3) * STAGE_B;
        uint32_t Bs = As + BHI_OFF;

#pragma unroll
        for (int k16 = 0; k16 < 2; k16++) {
            uint32_t ahi[4][4], alo[4][4];
#pragma unroll
            for (int mi = 0; mi < 4; mi++) {
                uint32_t a = As + (arow + mi * 16) * (PADROW * 2) + k16 * 32 + acolb;
                ldsm_x4(ahi[mi], a + AHI_OFF);
                ldsm_x4(alo[mi], a + ALO_OFF);
            }
#pragma unroll
            for (int ni = 0; ni < 4; ni++) {
                uint32_t bhi[2], blo[2];
                uint32_t ba = Bs + (bnrow + ni * 8) * (PADROW * 2) + k16 * 32 + bkoff;
                ldsm_x2(bhi, ba);
                ldsm_x2(blo, ba + (BLO_OFF - BHI_OFF));
#pragma unroll
                for (int mi = 0; mi < 4; mi++) {
                    mma_bf16(acc[mi][ni], ahi[mi], bhi);
                    mma_bf16(acc[mi][ni], alo[mi], bhi);
                    mma_bf16(acc[mi][ni], ahi[mi], blo);
                }
            }
        }

        // A conversion + STS after compute (LDG data has arrived by now);
        // consumed at iter it+2 after its top syncthreads.
        if (it + 2 < 8) stA(sNext);
    }

    // ---- epilogue: stage 32-row chunks in smem, write g_xp coalesced ----
    asm volatile("cp.async.wait_group 0;" ::: "memory");
    __syncthreads();
    float* stage = (float*)dsm;   // 32*256 floats = 32 KB
#pragma unroll
    for (int c = 0; c < 4; c++) {
        if (wm == (c >> 1)) {
#pragma unroll
            for (int mm = 0; mm < 2; mm++) {
                int mi = (c & 1) * 2 + mm;
                int lrow = mi * 16 + (lid >> 2) - (c & 1) * 32;
#pragma unroll
                for (int ni = 0; ni < 4; ni++) {
                    int n = wn * 32 + ni * 8 + (lid & 3) * 2;
                    float b0 = bias_s[n], b1 = bias_s[n + 1];
                    *(float2*)&stage[lrow * 256 + n] =
                        make_float2(acc[mi][ni][0] + b0, acc[mi][ni][1] + b1);
                    *(float2*)&stage[(lrow + 8) * 256 + n] =
                        make_float2(acc[mi][ni][2] + b0, acc[mi][ni][3] + b1);
                }
            }
        }
        __syncthreads();
        {
            int lrow = tid >> 4;
            int col  = (tid & 15) * 16;
            size_t r = r0 + c * 32 + lrow;
            int t = (int)(r & 2047), b = (int)(r >> 11);
            float* dst = &g_xp[((size_t)t * BATCH + b) * HID + col];
            const float4* srcp = (const float4*)&stage[lrow * 256 + col];
#pragma unroll
            for (int q = 0; q < 4; q++) ((float4*)dst)[q] = srcp[q];
        }
        __syncthreads();
    }
}

// ---------------------------------------------------------------------------
// Kernel 2: warp-uniform K-split recurrence (R14 winner, unchanged).
// 128 CTAs x 256 threads (8 warps). Warps 0-3 = K-half 0, warps 4-7 = K-half 1.
// Thread idx = tid & 127 owns columns jA = idx, jB = idx + 128 over its
// 128-row K-range: rows [kbase, kbase+64) in registers (u64 k-pairs),
// rows [kbase+64, kbase+128) in smem quads [group][j][4].
// smem: W 32 groups * 4096 = 131072 | h 2*1024 @131072 | xbuf 2*1024 @133120
// ---------------------------------------------------------------------------
#define RH_OFF  131072
#define RX_OFF  133120
#define RSMEM   135168

__global__ __launch_bounds__(256, 1)
void rnn_recurrence_kernel(const float* __restrict__ W_hh) {
    extern __shared__ __align__(16) char sm[];

    const int tid  = threadIdx.x;
    const int half = tid >> 7;
    const int idx  = tid & 127;
    const int jA   = idx;
    const int jB   = idx + 128;
    const int b0   = blockIdx.x * 2;
    const int kbase = half * 128;

    for (int e = tid; e < 32 * 256; e += 256) {
        int g = e >> 8;
        int j = e & 255;
        int h = g >> 4, q = g & 15;
        int row = h * 128 + 64 + 4 * q;
        float4 v;
        v.x = W_hh[(row + 0) * 256 + j];
        v.y = W_hh[(row + 1) * 256 + j];
        v.z = W_hh[(row + 2) * 256 + j];
        v.w = W_hh[(row + 3) * 256 + j];
        *(float4*)(sm + g * 4096 + j * 16) = v;
    }

    unsigned long long wA[32], wB[32];
#pragma unroll
    for (int r = 0; r < 32; r++) {
        wA[r] = f32x2_pack(W_hh[(kbase + 2 * r) * 256 + jA],
                           W_hh[(kbase + 2 * r + 1) * 256 + jA]);
        wB[r] = f32x2_pack(W_hh[(kbase + 2 * r) * 256 + jB],
                           W_hh[(kbase + 2 * r + 1) * 256 + jB]);
    }

    ((float*)(sm + RH_OFF))[tid] = 0.f;
    ((float*)(sm + RH_OFF))[tid + 256] = 0.f;
    __syncthreads();

    const float* xpA = g_xp + (size_t)(b0 + half) * HID + jA;
    float pA = xpA[0];
    float pB = xpA[128];

    const char* hb0 = sm + RH_OFF + kbase * 4;
    const char* hb1 = sm + RH_OFF + 1024 + kbase * 4;
    const char* wsm = sm + half * 16 * 4096;

    float hA = 0.f, hB = 0.f;

    for (int t = 0; t < T_STEPS; t++) {
        unsigned long long aA0x = 0, aA0y = 0, aA1x = 0, aA1y = 0;
        unsigned long long aB0x = 0, aB0y = 0, aB1x = 0, aB1y = 0;

        int tn = (t + 1 < T_STEPS) ? (t + 1) : t;
        float pAn = xpA[(size_t)tn * (BATCH * HID)];
        float pBn = xpA[(size_t)tn * (BATCH * HID) + 128];

#pragma unroll
        for (int q = 0; q < 16; q++) {
            ulonglong2 h0 = *(const ulonglong2*)(hb0 + q * 16);
            ulonglong2 h1 = *(const ulonglong2*)(hb1 + q * 16);
            ffma2(aA0x, h0.x, wA[2 * q]);
            ffma2(aA0y, h0.y, wA[2 * q + 1]);
            ffma2(aA1x, h1.x, wA[2 * q]);
            ffma2(aA1y, h1.y, wA[2 * q + 1]);
            ffma2(aB0x, h0.x, wB[2 * q]);
            ffma2(aB0y, h0.y, wB[2 * q + 1]);
            ffma2(aB1x, h1.x, wB[2 * q]);
            ffma2(aB1y, h1.y, wB[2 * q + 1]);
        }
#pragma unroll
        for (int q = 0; q < 16; q++) {
            ulonglong2 wqA = *(const ulonglong2*)(wsm + q * 4096 + jA * 16);
            ulonglong2 wqB = *(const ulonglong2*)(wsm + q * 4096 + jB * 16);
            ulonglong2 h0  = *(const ulonglong2*)(hb0 + 256 + q * 16);
            ulonglong2 h1  = *(const ulonglong2*)(hb1 + 256 + q * 16);
            ffma2(aA0x, h0.x, wqA.x);
            ffma2(aA0y, h0.y, wqA.y);
            ffma2(aA1x, h1.x, wqA.x);
            ffma2(aA1y, h1.y, wqA.y);
            ffma2(aB0x, h0.x, wqB.x);
            ffma2(aB0y, h0.y, wqB.y);
            ffma2(aB1x, h1.x, wqB.x);
            ffma2(aB1y, h1.y, wqB.y);
        }

        fadd2(aA0x, aA0y);
        fadd2(aA1x, aA1y);
        fadd2(aB0x, aB0y);
        fadd2(aB1x, aB1y);
        float lo, hi;
        f32x2_unpack(aA0x, lo, hi); float sA0 = lo + hi;
        f32x2_unpack(aA1x, lo, hi); float sA1 = lo + hi;
        f32x2_unpack(aB0x, lo, hi); float sB0 = lo + hi;
        f32x2_unpack(aB1x, lo, hi); float sB1 = lo + hi;

        float2* xb = (float2*)(sm + RX_OFF + half * 1024) + idx;
        *xb = (half == 0) ? make_float2(sA1, sB1) : make_float2(sA0, sB0);
        __syncthreads();
        float2 other = *((const float2*)(sm + RX_OFF + (half ^ 1) * 1024) + idx);
        float totA = ((half == 0) ? sA0 : sA1) + other.x + pA;
        float totB = ((half == 0) ? sB0 : sB1) + other.y + pB;
        hA = fast_tanh(totA);
        hB = fast_tanh(totB);
        pA = pAn;
        pB = pBn;
        float* hrow = (float*)(sm + RH_OFF + half * 1024);
        hrow[jA] = hA;
        hrow[jB] = hB;
        __syncthreads();
    }

    g_hfinal[(size_t)(b0 + half) * HID + jA] = hA;
    g_hfinal[(size_t)(b0 + half) * HID + jB] = hB;
}

// ---------------------------------------------------------------------------
// Kernel 3: classifier head (tiny)
// ---------------------------------------------------------------------------
__global__ __launch_bounds__(128)
void rnn_head_kernel(const float* __restrict__ fcw,
                     const float* __restrict__ fcb,
                     float* __restrict__ out) {
    __shared__ float hs[HID];
    __shared__ float part[8][OUT_DIM];
    const int b = blockIdx.x;
    const int tid = threadIdx.x;

    hs[tid]       = g_hfinal[(size_t)b * HID + tid];
    hs[tid + 128] = g_hfinal[(size_t)b * HID + tid + 128];
    __syncthreads();

    const int o   = tid & 15;
    const int seg = tid >> 4;
    float s = 0.f;
#pragma unroll
    for (int jj = 0; jj < 32; jj++) {
        int j = seg * 32 + jj;
        s += hs[j] * fcw[o * HID + j];
    }
    part[seg][o] = s;
    __syncthreads();
    if (tid < OUT_DIM) {
        float r = fcb[tid];
#pragma unroll
        for (int sg = 0; sg < 8; sg++) r += part[sg][tid];
        out[b * OUT_DIM + tid] = r;
    }
}

// ---------------------------------------------------------------------------
extern "C" void kernel_launch(void* const* d_in, const int* in_sizes, int n_in,
                              void* d_out, int out_size) {
    const float* x   = (const float*)d_in[0];
    const float* Wih = (const float*)d_in[1];
    const float* Whh = (const float*)d_in[2];
    const float* bh  = (const float*)d_in[3];
    const float* fcw = (const float*)d_in[4];
    const float* fcb = (const float*)d_in[5];
    float* out = (float*)d_out;

    // 0) bf16 hi/lo split of W_ih^T only (x converted inside the GEMM)
    prep_w_kernel<<<256, 256>>>(Wih);

    // 1) input projection GEMM (mma.sync, 3-stage pipeline) -> g_xp
    cudaFuncSetAttribute(gemm_xp_mma_kernel,
                         cudaFuncAttributeMaxDynamicSharedMemorySize, GSMEM);
    gemm_xp_mma_kernel<<<(BATCH * T_STEPS) / 128, 512, GSMEM>>>(x, bh);

    // 2) persistent recurrence (R14 winner, unchanged)
    cudaFuncSetAttribute(rnn_recurrence_kernel,
                         cudaFuncAttributeMaxDynamicSharedMemorySize, RSMEM);
    rnn_recurrence_kernel<<<BATCH / 2, 256, RSMEM>>>(Whh);

    // 3) classifier head
    rnn_head_kernel<<<BATCH, 128>>>(fcw, fcb, out);
}